// round 15
// baseline (speedup 1.0000x reference)
#include <cuda_runtime.h>
#include <cstdint>

#define Bn 128
#define Ln 512
#define En 512
#define Hn 256
#define G4 1024
#define Kn 64

// ---------------- scratch (static device allocations) ----------------
__device__ uint32_t g_preB[2][Ln][Bn][G4/2];   // 268MB: pre-activations bf16x2 [dir][t][b][gate_pair]
__device__ uint32_t g_histB[Ln][Bn][Hn];       // 67MB: concat hidden states bf16x2 [t][b][h_pair]
__device__ float g_emit[Bn][Ln][Kn];           // emissions [b][t][k]
__device__ uint32_t g_xb[Bn][Ln][En/2];        // 67MB: x in bf16x2
__device__ uint32_t g_wihb2[2][G4][En/2];      // W_ih bf16x2 (2MB)
__device__ uint32_t g_wemb[Kn][En/2];          // w_emit bf16x2 (64KB)

__device__ __forceinline__ float sigf(float x) {
    return 1.0f / (1.0f + __expf(-x));
}
__device__ __forceinline__ float tanhfast(float x) {
    float e = __expf(2.0f * x);
    return 1.0f - __fdividef(2.0f, e + 1.0f);
}

__device__ __forceinline__ uint32_t pack_bf16(float lo, float hi) {
    uint32_t r;
    asm("cvt.rn.bf16x2.f32 %0, %1, %2;" : "=r"(r) : "f"(hi), "f"(lo));
    return r;
}
__device__ __forceinline__ float bflo(uint32_t w) { return __uint_as_float(w << 16); }
__device__ __forceinline__ float bfhi(uint32_t w) { return __uint_as_float(w & 0xffff0000u); }

__device__ __forceinline__ void mma_bf16(float* d, const uint32_t* a, const uint32_t* b) {
    asm volatile(
        "mma.sync.aligned.m16n8k16.row.col.f32.bf16.bf16.f32 "
        "{%0,%1,%2,%3}, {%4,%5,%6,%7}, {%8,%9}, {%0,%1,%2,%3};"
        : "+f"(d[0]), "+f"(d[1]), "+f"(d[2]), "+f"(d[3])
        : "r"(a[0]), "r"(a[1]), "r"(a[2]), "r"(a[3]), "r"(b[0]), "r"(b[1]));
}

__device__ __forceinline__ uint32_t smem_u32(const void* p) {
    uint32_t a;
    asm("{ .reg .u64 t; cvta.to.shared.u64 t, %1; cvt.u32.u64 %0, t; }" : "=r"(a) : "l"(p));
    return a;
}

#define LDSM4(d, a)                                                            \
    asm volatile("ldmatrix.sync.aligned.m8n8.x4.shared.b16 {%0,%1,%2,%3}, [%4];" \
        : "=r"((d)[0]), "=r"((d)[1]), "=r"((d)[2]), "=r"((d)[3]) : "r"(a))

#define CP_ASYNC16(dst, src) \
    asm volatile("cp.async.cg.shared.global [%0], [%1], 16;" :: "r"(dst), "l"(src) : "memory")
#define CP_COMMIT() asm volatile("cp.async.commit_group;" ::: "memory")
#define CP_WAIT(n)  asm volatile("cp.async.wait_group %0;" :: "n"(n) : "memory")

// ---------------- 0) prep: fp32 -> bf16x2 conversions ----------------
__global__ void __launch_bounds__(256) k_cvt_x(const float* __restrict__ x) {
    uint32_t* dst = &g_xb[0][0][0];
    int i = blockIdx.x * 512 + threadIdx.x * 2;     // 2 float4 per thread
#pragma unroll
    for (int j = 0; j < 2; j++) {
        int f = i + j;
        float4 v = *(const float4*)(x + (size_t)f * 4);
        *(uint2*)(dst + (size_t)f * 2) = make_uint2(pack_bf16(v.x, v.y), pack_bf16(v.z, v.w));
    }
}

#define WF4 131072      // 1024*512/4
__global__ void __launch_bounds__(256) k_cvt_w(
    const float* __restrict__ wf, const float* __restrict__ wb,
    const float* __restrict__ wem)
{
    int f = blockIdx.x * 256 + threadIdx.x;          // float4 index
    const float* src;
    uint32_t* dst;
    if (f < WF4)           { src = wf;  dst = &g_wihb2[0][0][0]; }
    else if (f < 2 * WF4)  { src = wb;  dst = &g_wihb2[1][0][0]; f -= WF4; }
    else                   { src = wem; dst = &g_wemb[0][0];     f -= 2 * WF4;
                             if (f >= Kn * En / 4) return; }
    float4 v = *(const float4*)(src + (size_t)f * 4);
    *(uint2*)(dst + (size_t)f * 2) = make_uint2(pack_bf16(v.x, v.y), pack_bf16(v.z, v.w));
}

__global__ void k_nop() {}

// ---------------- 1) input GEMM (mma.sync bf16, 64x64 warp tiles, cp.async) ----------------
// C tile: M=128 batch x N=128 gates, 4 warps of 64x64. K=512 in 16 stages of 32.
// SMEM [row][k2], 20-word stride (LDSM conflict-free). Staging via cp.async (no STS, no regs).
#define RS 20
#define BUFW (128 * RS)

__global__ void __launch_bounds__(128) k_gemm_bf16(
    const float* __restrict__ bihf, const float* __restrict__ bhhf,
    const float* __restrict__ bihb, const float* __restrict__ bhhb)
{
    const int gtile = blockIdx.x;           // 0..7
    const int t     = blockIdx.y;           // 0..511
    const int dir   = blockIdx.z;           // 0,1
    const int t_eff = dir ? (Ln - 1 - t) : t;
    const int g0 = gtile * 128;

    __shared__ uint32_t As[2 * BUFW];       // x tile [buf][row b][k2]
    __shared__ uint32_t Bs[2 * BUFW];       // W tile [buf][row g][k2]

    const int tid  = threadIdx.x;
    const int wid  = tid >> 5;
    const int lane = tid & 31;
    const int wm   = (wid >> 1) * 64;   // warp M (batch) base
    const int wn   = (wid & 1) * 64;    // warp N (gate) base
    const int grp  = lane >> 2;
    const int qk   = lane & 3;

    // ldmatrix per-lane source coords (same verified pattern as R14)
    const int lane15 = lane & 15;
    const int acol   = (lane & 16) ? 4 : 0;
    const int browb  = ((lane & 16) >> 1) + (lane & 7);
    const int bcol   = (lane & 8) ? 4 : 0;

    const uint32_t baseA = smem_u32(As);
    const uint32_t baseB = smem_u32(Bs);
    uint32_t aoff[4], boff[4];
#pragma unroll
    for (int mi = 0; mi < 4; mi++)
        aoff[mi] = (uint32_t)((wm + mi * 16 + lane15) * RS + acol);
#pragma unroll
    for (int j = 0; j < 4; j++)
        boff[j] = (uint32_t)((wn + j * 16 + browb) * RS + bcol);

    // cp.async staging: thread owns A row tid and B row tid (4 x 16B each per stage)
    const uint32_t* __restrict__ xsrc = &g_xb[tid][t_eff][0];
    const uint32_t* __restrict__ wsrc = &g_wihb2[dir][g0 + tid][0];
    const uint32_t dstA0 = baseA + (uint32_t)(tid * RS) * 4;
    const uint32_t dstB0 = baseB + (uint32_t)(tid * RS) * 4;

#define COPY(s) do {                                                           \
        const uint32_t bo = (uint32_t)(((s) & 1) * BUFW) * 4;                  \
        const uint32_t* sA = xsrc + (s) * 16;                                  \
        const uint32_t* sB = wsrc + (s) * 16;                                  \
        CP_ASYNC16(dstA0 + bo,      sA);                                       \
        CP_ASYNC16(dstA0 + bo + 16, sA + 4);                                   \
        CP_ASYNC16(dstA0 + bo + 32, sA + 8);                                   \
        CP_ASYNC16(dstA0 + bo + 48, sA + 12);                                  \
        CP_ASYNC16(dstB0 + bo,      sB);                                       \
        CP_ASYNC16(dstB0 + bo + 16, sB + 4);                                   \
        CP_ASYNC16(dstB0 + bo + 32, sB + 8);                                   \
        CP_ASYNC16(dstB0 + bo + 48, sB + 12);                                  \
        CP_COMMIT();                                                           \
    } while (0)

    float acc[4][8][4];                 // [mi][ni][reg]
#pragma unroll
    for (int mi = 0; mi < 4; mi++)
#pragma unroll
        for (int ni = 0; ni < 8; ni++)
#pragma unroll
            for (int r = 0; r < 4; r++) acc[mi][ni][r] = 0.0f;

    COPY(0);

    for (int s = 0; s < 16; s++) {
        const uint32_t curw = (uint32_t)(s & 1) * BUFW;
        if (s < 15) { COPY(s + 1); CP_WAIT(1); }
        else        { CP_WAIT(0); }
        __syncthreads();

#pragma unroll
        for (int kc2 = 0; kc2 < 16; kc2 += 8) {
            uint32_t af[4][4], bt[4][4];
#pragma unroll
            for (int mi = 0; mi < 4; mi++)
                LDSM4(af[mi], baseA + (curw + aoff[mi] + kc2) * 4);
#pragma unroll
            for (int j = 0; j < 4; j++)
                LDSM4(bt[j], baseB + (curw + boff[j] + kc2) * 4);
#pragma unroll
            for (int mi = 0; mi < 4; mi++)
#pragma unroll
                for (int j = 0; j < 4; j++) {
                    mma_bf16(acc[mi][2 * j],     af[mi], bt[j]);
                    mma_bf16(acc[mi][2 * j + 1], af[mi], bt[j] + 2);
                }
        }
        __syncthreads();                // all reads of buf (s&1) done before copy(s+2)
    }
#undef COPY

    // epilogue
    const float* __restrict__ bih = dir ? bihb : bihf;
    const float* __restrict__ bhh = dir ? bhhb : bhhf;
#pragma unroll
    for (int ni = 0; ni < 8; ni++) {
        int gate0 = g0 + wn + ni * 8 + 2 * qk;
        float bias0 = bih[gate0] + bhh[gate0];
        float bias1 = bih[gate0 + 1] + bhh[gate0 + 1];
        int g2w = (g0 + wn + ni * 8) / 2 + qk;
#pragma unroll
        for (int mi = 0; mi < 4; mi++) {
            int bA = wm + mi * 16 + grp;
            g_preB[dir][t][bA][g2w]     = pack_bf16(acc[mi][ni][0] + bias0, acc[mi][ni][1] + bias1);
            g_preB[dir][t][bA + 8][g2w] = pack_bf16(acc[mi][ni][2] + bias0, acc[mi][ni][3] + bias1);
        }
    }
}

// ---------------- 2) LSTM recurrence: 8-CTA cluster, DSMEM h-exchange, split acc chains ----------------
__global__ void __launch_bounds__(256) __cluster_dims__(8, 1, 1) k_lstm4(
    const float* __restrict__ whf, const float* __restrict__ whb)
{
    const int dir  = blockIdx.x >> 6;
    const int sub  = blockIdx.x & 63;
    const int bblk = sub >> 3;
    const int gs   = sub & 7;                // == cluster rank
    const float* __restrict__ whh = dir ? whb : whf;

    const int tid  = threadIdx.x;
    const int wid  = tid >> 5;
    const int lane = tid & 31;
    const int grp  = lane >> 2;
    const int qk   = lane & 3;
    const int bm   = bblk * 16;              // CTA batch base
    const int m0w  = gs * 32 + wid * 4;      // warp's 4 hidden units

    // h staging, double-buffered: [parity][k2 row 0..127][b col 0..15], stride 24 (conflict-free reads)
    __shared__ uint32_t hsm[2][128 * 24];    // 24.6 KB

    // ---- B fragments (W_hh slice for this warp), persistent in registers ----
    uint32_t B0[2][16], B1[2][16];
#pragma unroll
    for (int nt = 0; nt < 2; nt++) {
        int c = nt * 8 + grp;                          // warp col 0..15
        int gcol = (c >> 2) * 256 + m0w + (c & 3);     // global gate
        const float* wr = whh + (size_t)gcol * Hn;
#pragma unroll
        for (int kb = 0; kb < 16; kb++) {
            float2 w0 = *(const float2*)(wr + kb * 16 + 2 * qk);
            float2 w1 = *(const float2*)(wr + kb * 16 + 8 + 2 * qk);
            B0[nt][kb] = pack_bf16(w0.x, w0.y);
            B1[nt][kb] = pack_bf16(w1.x, w1.y);
        }
    }

    float cst0 = 0.0f, cst1 = 0.0f;                   // cell state (2 per lane)
    const int rb      = (qk >= 2) ? 2 : 0;
    const int b_loc   = grp + ((qk >= 2) ? 8 : 0);    // local batch col 0..15
    const int b_row   = bm + b_loc;
    const int m2w     = gs * 16 + wid * 2 + (qk & 1); // global k2 row 0..127
    const int hwrd    = dir * 128 + m2w;              // hist word col

    const int wrd0 = ((qk >> 1)) * 128 + m2w;       // nt=0 preB word
    const int wrd1 = (2 + (qk >> 1)) * 128 + m2w;   // nt=1 preB word

    const uint32_t ha0 = smem_u32(&hsm[0][m2w * 24 + b_loc]);
    const uint32_t ha1 = smem_u32(&hsm[1][m2w * 24 + b_loc]);

    // prefetch preB for t=0
    uint32_t pw[4];
    pw[0] = g_preB[dir][0][bm + grp][wrd0];
    pw[1] = g_preB[dir][0][bm + grp + 8][wrd0];
    pw[2] = g_preB[dir][0][bm + grp][wrd1];
    pw[3] = g_preB[dir][0][bm + grp + 8][wrd1];

    for (int t = 0; t < Ln; t++) {
        float acc[2][4], acd[2][4];      // even-kb and odd-kb accumulator chains
#pragma unroll
        for (int nt = 0; nt < 2; nt++)
#pragma unroll
            for (int r = 0; r < 4; r++) { acc[nt][r] = 0.0f; acd[nt][r] = 0.0f; }

        if (t > 0) {
            const uint32_t* __restrict__ hb = &hsm[(t - 1) & 1][0];
#pragma unroll
            for (int kb = 0; kb < 16; kb++) {
                uint32_t a[4];
                const int r0 = (kb * 8 + qk) * 24;
                a[0] = hb[r0 + grp];
                a[1] = hb[r0 + grp + 8];
                a[2] = hb[r0 + 96 + grp];        // +4 rows
                a[3] = hb[r0 + 96 + grp + 8];
                uint32_t b0[2] = {B0[0][kb], B1[0][kb]};
                uint32_t b1[2] = {B0[1][kb], B1[1][kb]};
                float* d0 = (kb & 1) ? acd[0] : acc[0];
                float* d1 = (kb & 1) ? acd[1] : acc[1];
                mma_bf16(d0, a, b0);
                mma_bf16(d1, a, b1);
            }
#pragma unroll
            for (int nt = 0; nt < 2; nt++)
#pragma unroll
                for (int r = 0; r < 4; r++) acc[nt][r] += acd[nt][r];
        }

        // add pre-activations (prefetched)
        acc[0][0] += bflo(pw[0]); acc[0][1] += bfhi(pw[0]);
        acc[0][2] += bflo(pw[1]); acc[0][3] += bfhi(pw[1]);
        acc[1][0] += bflo(pw[2]); acc[1][1] += bfhi(pw[2]);
        acc[1][2] += bflo(pw[3]); acc[1][3] += bfhi(pw[3]);

        // exchange with lane^2: (i,g) <-> (f,o)
        float recv[2][4];
#pragma unroll
        for (int nt = 0; nt < 2; nt++)
#pragma unroll
            for (int r = 0; r < 4; r++)
                recv[nt][r] = __shfl_xor_sync(0xffffffffu, acc[nt][r], 2);

        const bool ig = (qk < 2);
        float h0, h1;
        {
            float i_ = ig ? acc[0][rb + 0] : recv[0][rb + 0];
            float f_ = ig ? recv[0][rb + 0] : acc[0][rb + 0];
            float g_ = ig ? acc[1][rb + 0] : recv[1][rb + 0];
            float o_ = ig ? recv[1][rb + 0] : acc[1][rb + 0];
            cst0 = sigf(f_) * cst0 + sigf(i_) * tanhfast(g_);
            h0 = sigf(o_) * tanhfast(cst0);
        }
        {
            float i_ = ig ? acc[0][rb + 1] : recv[0][rb + 1];
            float f_ = ig ? recv[0][rb + 1] : acc[0][rb + 1];
            float g_ = ig ? acc[1][rb + 1] : recv[1][rb + 1];
            float o_ = ig ? recv[1][rb + 1] : acc[1][rb + 1];
            cst1 = sigf(f_) * cst1 + sigf(i_) * tanhfast(g_);
            h1 = sigf(o_) * tanhfast(cst1);
        }

        const uint32_t hw = pack_bf16(h0, h1);
        const int rt = dir ? (Ln - 1 - t) : t;
        __stcg(&g_histB[rt][b_row][hwrd], hw);

        if (t != Ln - 1) {
            // multicast h word to all 8 cluster CTAs (skipped on the last step: dead +
            // would race peer CTA exit)
            const uint32_t laddr = (t & 1) ? ha1 : ha0;
#pragma unroll
            for (int r = 0; r < 8; r++) {
                uint32_t raddr;
                asm("mapa.shared::cluster.u32 %0, %1, %2;" : "=r"(raddr) : "r"(laddr), "r"(r));
                asm volatile("st.shared::cluster.u32 [%0], %1;" :: "r"(raddr), "r"(hw) : "memory");
            }
            // prefetch next step's preB before the barrier (no dependency)
            pw[0] = __ldcg(&g_preB[dir][t + 1][bm + grp][wrd0]);
            pw[1] = __ldcg(&g_preB[dir][t + 1][bm + grp + 8][wrd0]);
            pw[2] = __ldcg(&g_preB[dir][t + 1][bm + grp][wrd1]);
            pw[3] = __ldcg(&g_preB[dir][t + 1][bm + grp + 8][wrd1]);
            asm volatile("barrier.cluster.arrive.aligned;" ::: "memory");
            asm volatile("barrier.cluster.wait.aligned;" ::: "memory");
        }
    }

    // trailing cluster barrier: no CTA exits while any peer's remote traffic could be in flight
    asm volatile("barrier.cluster.arrive.aligned;" ::: "memory");
    asm volatile("barrier.cluster.wait.aligned;" ::: "memory");
}

// ---------------- 3) emit GEMM (mma bf16): emit[b][t][k] = histB[t][b] @ wemb^T + b_emit ----------------
__global__ void __launch_bounds__(256) k_emit2(const float* __restrict__ bem)
{
    const int t = blockIdx.x;
    __shared__ uint32_t As2[32][136];   // [k2][b]
    __shared__ uint32_t Bs2[32][72];    // [k2][k-col]

    const int tid  = threadIdx.x;
    const int wid  = tid >> 5;
    const int lane = tid & 31;
    const int grp  = lane >> 2;
    const int qk   = lane & 3;
    const int wm   = wid * 16;          // warp batch base

    float acc[8][4];
#pragma unroll
    for (int nb = 0; nb < 8; nb++)
#pragma unroll
        for (int r = 0; r < 4; r++) acc[nb][r] = 0.0f;

    for (int c = 0; c < 8; c++) {                  // K chunks: 64 h (32 words)
        const int k0w = c * 32;
#pragma unroll
        for (int i = 0; i < 4; i++) {              // A: 128 rows x 32 words
            int idx = (i << 8) + tid;
            int r   = idx >> 3;                    // 0..127
            int q   = idx & 7;
            uint4 v = *(const uint4*)&g_histB[t][r][k0w + q * 4];
            As2[q * 4 + 0][r] = v.x; As2[q * 4 + 1][r] = v.y;
            As2[q * 4 + 2][r] = v.z; As2[q * 4 + 3][r] = v.w;
        }
#pragma unroll
        for (int i = 0; i < 2; i++) {              // B: 64 rows x 32 words
            int idx = (i << 8) + tid;
            int r   = idx >> 3;                    // 0..63
            int q   = idx & 7;
            uint4 v = *(const uint4*)&g_wemb[r][k0w + q * 4];
            Bs2[q * 4 + 0][r] = v.x; Bs2[q * 4 + 1][r] = v.y;
            Bs2[q * 4 + 2][r] = v.z; Bs2[q * 4 + 3][r] = v.w;
        }
        __syncthreads();
#pragma unroll
        for (int kb = 0; kb < 4; kb++) {
            int k2 = kb * 8;
            uint32_t a[4];
            a[0] = As2[k2 + qk][wm + grp];
            a[1] = As2[k2 + qk][wm + grp + 8];
            a[2] = As2[k2 + 4 + qk][wm + grp];
            a[3] = As2[k2 + 4 + qk][wm + grp + 8];
#pragma unroll
            for (int nb = 0; nb < 8; nb++) {
                uint32_t b[2] = {Bs2[k2 + qk][nb * 8 + grp], Bs2[k2 + 4 + qk][nb * 8 + grp]};
                mma_bf16(acc[nb], a, b);
            }
        }
        __syncthreads();
    }

#pragma unroll
    for (int nb = 0; nb < 8; nb++) {
        int k = nb * 8 + qk * 2;
        float b0 = bem[k], b1 = bem[k + 1];
        *(float2*)&g_emit[wm + grp][t][k]     = make_float2(acc[nb][0] + b0, acc[nb][1] + b1);
        *(float2*)&g_emit[wm + grp + 8][t][k] = make_float2(acc[nb][2] + b0, acc[nb][3] + b1);
    }
}

// ---------------- 4) CRF forward + gold score: warp per batch, reduction-free shift ----------------
__global__ void __launch_bounds__(32) k_crf(
    const int* __restrict__ labels,
    const float* __restrict__ trans,
    float* __restrict__ out)
{
    const int b = blockIdx.x;
    const int lane = threadIdx.x;
    __shared__ float ps[64];

    float eTc0[64], eTc1[64];
#pragma unroll 8
    for (int i = 0; i < 64; i++) {
        eTc0[i] = __expf(trans[i * 64 + lane]);
        eTc1[i] = __expf(trans[i * 64 + lane + 32]);
    }

    float d0 = g_emit[b][0][lane];
    float d1 = g_emit[b][0][lane + 32];
    float Cacc = 0.0f, Ckah = 0.0f;

    for (int t = 1; t < Ln; t++) {
        float c = __shfl_sync(0xffffffffu, d0, 0);
        ps[lane]      = __expf(d0 - c);
        ps[lane + 32] = __expf(d1 - c);
        __syncwarp();
        float s0a = 0.f, s0b = 0.f, s1a = 0.f, s1b = 0.f;
#pragma unroll
        for (int i = 0; i < 64; i += 2) {
            float pi = ps[i], pj = ps[i + 1];
            s0a = fmaf(pi, eTc0[i], s0a);
            s0b = fmaf(pj, eTc0[i + 1], s0b);
            s1a = fmaf(pi, eTc1[i], s1a);
            s1b = fmaf(pj, eTc1[i + 1], s1b);
        }
        d0 = g_emit[b][t][lane]      + __logf(s0a + s0b);
        d1 = g_emit[b][t][lane + 32] + __logf(s1a + s1b);
        float y = c - Ckah;
        float tt = Cacc + y;
        Ckah = (tt - Cacc) - y;
        Cacc = tt;
        __syncwarp();
    }

    float m = fmaxf(d0, d1);
#pragma unroll
    for (int o = 16; o > 0; o >>= 1)
        m = fmaxf(m, __shfl_xor_sync(0xffffffffu, m, o));
    float sp = __expf(d0 - m) + __expf(d1 - m);
#pragma unroll
    for (int o = 16; o > 0; o >>= 1)
        sp += __shfl_xor_sync(0xffffffffu, sp, o);
    float logz = m + __logf(sp) + Cacc;

    float gold = 0.0f;
    for (int t = lane; t < Ln; t += 32) {
        int lab = labels[b * Ln + t];
        gold += g_emit[b][t][lab];
        if (t < Ln - 1) {
            int lab2 = labels[b * Ln + t + 1];
            gold += trans[lab * 64 + lab2];
        }
    }
#pragma unroll
    for (int o = 16; o > 0; o >>= 1)
        gold += __shfl_xor_sync(0xffffffffu, gold, o);

    if (lane == 0) out[b] = logz - gold;
}

// ---------------- launch ----------------
extern "C" void kernel_launch(void* const* d_in, const int* in_sizes, int n_in,
                              void* d_out, int out_size)
{
    const float* x     = (const float*)d_in[0];
    const int*   lab   = (const int*)d_in[1];
    const float* wihf  = (const float*)d_in[2];
    const float* whhf  = (const float*)d_in[3];
    const float* bihf  = (const float*)d_in[4];
    const float* bhhf  = (const float*)d_in[5];
    const float* wihb  = (const float*)d_in[6];
    const float* whhb  = (const float*)d_in[7];
    const float* bihb  = (const float*)d_in[8];
    const float* bhhb  = (const float*)d_in[9];
    const float* wem   = (const float*)d_in[10];
    const float* bem   = (const float*)d_in[11];
    const float* trans = (const float*)d_in[12];
    float* out = (float*)d_out;

    k_cvt_x<<<16384, 256>>>(x);
    k_cvt_w<<<1088, 256>>>(wihf, wihb, wem);
    k_nop<<<1, 32>>>();                               // keeps ncu capture slot on the GEMM
    dim3 gg(8, 512, 2);
    k_gemm_bf16<<<gg, 128>>>(bihf, bhhf, bihb, bhhb);
    k_lstm4<<<128, 256>>>(whhf, whhb);
    k_emit2<<<512, 256>>>(bem);
    k_crf<<<128, 32>>>(lab, trans, out);
}

// round 16
// speedup vs baseline: 1.2377x; 1.2377x over previous
#include <cuda_runtime.h>
#include <cstdint>

#define Bn 128
#define Ln 512
#define En 512
#define Hn 256
#define G4 1024
#define Kn 64

// ---------------- scratch (static device allocations) ----------------
__device__ uint32_t g_preB[2][Ln][Bn][G4/2];   // 268MB: pre-activations bf16x2 [dir][t][b][gate_pair]
__device__ uint32_t g_histB[Ln][Bn][Hn];       // 67MB: concat hidden states bf16x2 [t][b][h_pair]
__device__ float g_emit[Bn][Ln][Kn];           // emissions [b][t][k]
__device__ uint32_t g_xb[Bn][Ln][En/2];        // 67MB: x in bf16x2
__device__ uint32_t g_wihb2[2][G4][En/2];      // W_ih bf16x2 (2MB)
__device__ uint32_t g_wemb[Kn][En/2];          // w_emit bf16x2 (64KB)
__device__ unsigned int g_gdone[2][Ln];        // per-(dir,t) producer counters (reset each replay)

__device__ __forceinline__ float sigf(float x) {
    return 1.0f / (1.0f + __expf(-x));
}
__device__ __forceinline__ float tanhfast(float x) {
    float e = __expf(2.0f * x);
    return 1.0f - __fdividef(2.0f, e + 1.0f);
}

__device__ __forceinline__ uint32_t pack_bf16(float lo, float hi) {
    uint32_t r;
    asm("cvt.rn.bf16x2.f32 %0, %1, %2;" : "=r"(r) : "f"(hi), "f"(lo));
    return r;
}
__device__ __forceinline__ float bflo(uint32_t w) { return __uint_as_float(w << 16); }
__device__ __forceinline__ float bfhi(uint32_t w) { return __uint_as_float(w & 0xffff0000u); }

__device__ __forceinline__ void mma_bf16(float* d, const uint32_t* a, const uint32_t* b) {
    asm volatile(
        "mma.sync.aligned.m16n8k16.row.col.f32.bf16.bf16.f32 "
        "{%0,%1,%2,%3}, {%4,%5,%6,%7}, {%8,%9}, {%0,%1,%2,%3};"
        : "+f"(d[0]), "+f"(d[1]), "+f"(d[2]), "+f"(d[3])
        : "r"(a[0]), "r"(a[1]), "r"(a[2]), "r"(a[3]), "r"(b[0]), "r"(b[1]));
}

__device__ __forceinline__ uint32_t smem_u32(const void* p) {
    uint32_t a;
    asm("{ .reg .u64 t; cvta.to.shared.u64 t, %1; cvt.u32.u64 %0, t; }" : "=r"(a) : "l"(p));
    return a;
}

#define LDSM4(d, a)                                                            \
    asm volatile("ldmatrix.sync.aligned.m8n8.x4.shared.b16 {%0,%1,%2,%3}, [%4];" \
        : "=r"((d)[0]), "=r"((d)[1]), "=r"((d)[2]), "=r"((d)[3]) : "r"(a))

__device__ __forceinline__ void wait8(const unsigned int* p) {
    unsigned int v;
    while (true) {
        asm volatile("ld.acquire.gpu.global.u32 %0, [%1];" : "=r"(v) : "l"(p) : "memory");
        if (v >= 8u) break;
        __nanosleep(64);
    }
}

// ---------------- 0) prep: fp32 -> bf16x2 conversions (+ flag reset) ----------------
__global__ void __launch_bounds__(256) k_cvt_x(const float* __restrict__ x) {
    if (blockIdx.x == 0) {                          // reset producer counters each replay
        unsigned int* f = &g_gdone[0][0];
#pragma unroll
        for (int j = 0; j < 4; j++) f[threadIdx.x * 4 + j] = 0;
    }
    uint32_t* dst = &g_xb[0][0][0];
    int i = blockIdx.x * 512 + threadIdx.x * 2;     // 2 float4 per thread
#pragma unroll
    for (int j = 0; j < 2; j++) {
        int f = i + j;
        float4 v = *(const float4*)(x + (size_t)f * 4);
        *(uint2*)(dst + (size_t)f * 2) = make_uint2(pack_bf16(v.x, v.y), pack_bf16(v.z, v.w));
    }
}

#define WF4 131072      // 1024*512/4
__global__ void __launch_bounds__(256) k_cvt_w(
    const float* __restrict__ wf, const float* __restrict__ wb,
    const float* __restrict__ wem)
{
    int f = blockIdx.x * 256 + threadIdx.x;          // float4 index
    const float* src;
    uint32_t* dst;
    if (f < WF4)           { src = wf;  dst = &g_wihb2[0][0][0]; }
    else if (f < 2 * WF4)  { src = wb;  dst = &g_wihb2[1][0][0]; f -= WF4; }
    else                   { src = wem; dst = &g_wemb[0][0];     f -= 2 * WF4;
                             if (f >= Kn * En / 4) return; }
    float4 v = *(const float4*)(src + (size_t)f * 4);
    *(uint2*)(dst + (size_t)f * 2) = make_uint2(pack_bf16(v.x, v.y), pack_bf16(v.z, v.w));
}

__global__ void k_nop() {}

// ---------------- fused GEMM + LSTM ----------------
// grid 8320 CTAs, clusters of 8.
//   bids 0..127    : LSTM clusters (dir = b>>6, bblk = (b>>3)&7, gs = b&7 = rank)
//   bids 128..8319 : GEMM CTAs, lin = b-128: t = lin>>4, dir = (lin>>3)&1, gtile = lin&7
// GEMM CTAs release g_gdone[dir][t] (+1 each, 8 = complete); LSTM acquires before using preB[t].
#define RS 20
#define BUFW (128 * RS)

__global__ void __launch_bounds__(256, 2) __cluster_dims__(8, 1, 1) k_fused(
    const float* __restrict__ whf, const float* __restrict__ whb,
    const float* __restrict__ bihf, const float* __restrict__ bhhf,
    const float* __restrict__ bihb, const float* __restrict__ bhhb)
{
    __shared__ uint32_t sh[4 * BUFW];   // 40KB: gemm As|Bs double buffers; lstm uses first 24KB

    const int tid  = threadIdx.x;
    const int wid  = tid >> 5;
    const int lane = tid & 31;
    const int grp  = lane >> 2;
    const int qk   = lane & 3;

    if (blockIdx.x >= 128) {
        // ================= GEMM role (R14 proven version) =================
        const int lin   = blockIdx.x - 128;
        const int t     = lin >> 4;
        const int dir   = (lin >> 3) & 1;
        const int gtile = lin & 7;
        const int t_eff = dir ? (Ln - 1 - t) : t;
        const int g0 = gtile * 128;

        uint32_t* As = sh;
        uint32_t* Bs = sh + 2 * BUFW;

        const int wm = (wid >> 2) * 64;
        const int wn = (wid & 3) * 32;

        const int lane15 = lane & 15;
        const int acol   = (lane & 16) ? 4 : 0;
        const int brow0  = wn + ((lane & 16) >> 1) + (lane & 7);
        const int bcol   = (lane & 8) ? 4 : 0;

        const uint32_t baseA = smem_u32(As);
        const uint32_t baseB = smem_u32(Bs);
        uint32_t aoff[4];
#pragma unroll
        for (int mi = 0; mi < 4; mi++)
            aoff[mi] = (uint32_t)((wm + mi * 16 + lane15) * RS + acol);
        const uint32_t boff0 = (uint32_t)(brow0 * RS + bcol);
        const uint32_t boff1 = boff0 + 16 * RS;

        const int r0 = tid >> 2;
        const int r1 = r0 + 64;
        const int q  = tid & 3;
        const uint32_t* __restrict__ xa0 = &g_xb[r0][t_eff][q * 4];
        const uint32_t* __restrict__ xa1 = &g_xb[r1][t_eff][q * 4];
        const uint32_t* __restrict__ wa0 = &g_wihb2[dir][g0 + r0][q * 4];
        const uint32_t* __restrict__ wa1 = &g_wihb2[dir][g0 + r1][q * 4];

        uint4 va0, va1, vb0, vb1;
#define LOADG(s) do {                                      \
            va0 = *(const uint4*)(xa0 + (s) * 16);         \
            va1 = *(const uint4*)(xa1 + (s) * 16);         \
            vb0 = *(const uint4*)(wa0 + (s) * 16);         \
            vb1 = *(const uint4*)(wa1 + (s) * 16);         \
        } while (0)
#define STOREG(bu) do {                                                \
            *(uint4*)(As + (bu) * BUFW + r0 * RS + q * 4) = va0;       \
            *(uint4*)(As + (bu) * BUFW + r1 * RS + q * 4) = va1;       \
            *(uint4*)(Bs + (bu) * BUFW + r0 * RS + q * 4) = vb0;       \
            *(uint4*)(Bs + (bu) * BUFW + r1 * RS + q * 4) = vb1;       \
        } while (0)

        float acc[4][4][4];
#pragma unroll
        for (int mi = 0; mi < 4; mi++)
#pragma unroll
            for (int ni = 0; ni < 4; ni++)
#pragma unroll
                for (int r = 0; r < 4; r++) acc[mi][ni][r] = 0.0f;

        LOADG(0);
        STOREG(0);
        __syncthreads();

        for (int s = 0; s < 16; s++) {
            const uint32_t curw = (uint32_t)(s & 1) * BUFW;
            if (s < 15) LOADG(s + 1);

#pragma unroll
            for (int kc2 = 0; kc2 < 16; kc2 += 8) {
                uint32_t af[4][4];
#pragma unroll
                for (int mi = 0; mi < 4; mi++)
                    LDSM4(af[mi], baseA + (curw + aoff[mi] + kc2) * 4);
                uint32_t bt0[4], bt1[4];
                LDSM4(bt0, baseB + (curw + boff0 + kc2) * 4);
                LDSM4(bt1, baseB + (curw + boff1 + kc2) * 4);
#pragma unroll
                for (int mi = 0; mi < 4; mi++) {
                    mma_bf16(acc[mi][0], af[mi], bt0);
                    mma_bf16(acc[mi][1], af[mi], bt0 + 2);
                    mma_bf16(acc[mi][2], af[mi], bt1);
                    mma_bf16(acc[mi][3], af[mi], bt1 + 2);
                }
            }

            if (s < 15) {
                STOREG((s + 1) & 1);
                __syncthreads();
            }
        }
#undef LOADG
#undef STOREG

        const float* __restrict__ bih = dir ? bihb : bihf;
        const float* __restrict__ bhh = dir ? bhhb : bhhf;
#pragma unroll
        for (int ni = 0; ni < 4; ni++) {
            int gate0 = g0 + wn + ni * 8 + 2 * qk;
            float bias0 = bih[gate0] + bhh[gate0];
            float bias1 = bih[gate0 + 1] + bhh[gate0 + 1];
            int g2w = (g0 + wn + ni * 8) / 2 + qk;
#pragma unroll
            for (int mi = 0; mi < 4; mi++) {
                int bA = wm + mi * 16 + grp;
                g_preB[dir][t][bA][g2w]     = pack_bf16(acc[mi][ni][0] + bias0, acc[mi][ni][1] + bias1);
                g_preB[dir][t][bA + 8][g2w] = pack_bf16(acc[mi][ni][2] + bias0, acc[mi][ni][3] + bias1);
            }
        }

        // publish completion (release orders the preB stores of all threads via the bar)
        __syncthreads();
        if (tid == 0)
            asm volatile("red.add.release.gpu.global.u32 [%0], %1;"
                         :: "l"(&g_gdone[dir][t]), "r"(1u) : "memory");
        return;
    }

    // ================= LSTM role (R13/R14 proven version + producer pacing) =================
    {
        const int dir  = blockIdx.x >> 6;
        const int sub  = blockIdx.x & 63;
        const int bblk = sub >> 3;
        const int gs   = sub & 7;                // == cluster rank
        const float* __restrict__ whh = dir ? whb : whf;

        const int bm   = bblk * 16;
        const int m0w  = gs * 32 + wid * 4;

        uint32_t* hsm = sh;                      // [parity(3072 words)][k2 row][b], stride 24

        uint32_t B0[2][16], B1[2][16];
#pragma unroll
        for (int nt = 0; nt < 2; nt++) {
            int c = nt * 8 + grp;
            int gcol = (c >> 2) * 256 + m0w + (c & 3);
            const float* wr = whh + (size_t)gcol * Hn;
#pragma unroll
            for (int kb = 0; kb < 16; kb++) {
                float2 w0 = *(const float2*)(wr + kb * 16 + 2 * qk);
                float2 w1 = *(const float2*)(wr + kb * 16 + 8 + 2 * qk);
                B0[nt][kb] = pack_bf16(w0.x, w0.y);
                B1[nt][kb] = pack_bf16(w1.x, w1.y);
            }
        }

        float cst0 = 0.0f, cst1 = 0.0f;
        const int rb      = (qk >= 2) ? 2 : 0;
        const int b_loc   = grp + ((qk >= 2) ? 8 : 0);
        const int b_row   = bm + b_loc;
        const int m2w     = gs * 16 + wid * 2 + (qk & 1);
        const int hwrd    = dir * 128 + m2w;

        const int wrd0 = ((qk >> 1)) * 128 + m2w;
        const int wrd1 = (2 + (qk >> 1)) * 128 + m2w;

        const uint32_t ha0 = smem_u32(&hsm[m2w * 24 + b_loc]);
        const uint32_t ha1 = ha0 + 3072 * 4;

        // wait for preB[dir][0], then prefetch
        if (tid == 0) wait8(&g_gdone[dir][0]);
        __syncthreads();
        uint32_t pw[4];
        pw[0] = g_preB[dir][0][bm + grp][wrd0];
        pw[1] = g_preB[dir][0][bm + grp + 8][wrd0];
        pw[2] = g_preB[dir][0][bm + grp][wrd1];
        pw[3] = g_preB[dir][0][bm + grp + 8][wrd1];

        for (int t = 0; t < Ln; t++) {
            float acc[2][4], acd[2][4];
#pragma unroll
            for (int nt = 0; nt < 2; nt++)
#pragma unroll
                for (int r = 0; r < 4; r++) { acc[nt][r] = 0.0f; acd[nt][r] = 0.0f; }

            if (t > 0) {
                const uint32_t* __restrict__ hb = hsm + ((t - 1) & 1) * 3072;
#pragma unroll
                for (int kb = 0; kb < 16; kb++) {
                    uint32_t a[4];
                    const int r0 = (kb * 8 + qk) * 24;
                    a[0] = hb[r0 + grp];
                    a[1] = hb[r0 + grp + 8];
                    a[2] = hb[r0 + 96 + grp];
                    a[3] = hb[r0 + 96 + grp + 8];
                    uint32_t b0[2] = {B0[0][kb], B1[0][kb]};
                    uint32_t b1[2] = {B0[1][kb], B1[1][kb]};
                    float* d0 = (kb & 1) ? acd[0] : acc[0];
                    float* d1 = (kb & 1) ? acd[1] : acc[1];
                    mma_bf16(d0, a, b0);
                    mma_bf16(d1, a, b1);
                }
#pragma unroll
                for (int nt = 0; nt < 2; nt++)
#pragma unroll
                    for (int r = 0; r < 4; r++) acc[nt][r] += acd[nt][r];
            }

            acc[0][0] += bflo(pw[0]); acc[0][1] += bfhi(pw[0]);
            acc[0][2] += bflo(pw[1]); acc[0][3] += bfhi(pw[1]);
            acc[1][0] += bflo(pw[2]); acc[1][1] += bfhi(pw[2]);
            acc[1][2] += bflo(pw[3]); acc[1][3] += bfhi(pw[3]);

            float recv[2][4];
#pragma unroll
            for (int nt = 0; nt < 2; nt++)
#pragma unroll
                for (int r = 0; r < 4; r++)
                    recv[nt][r] = __shfl_xor_sync(0xffffffffu, acc[nt][r], 2);

            const bool ig = (qk < 2);
            float h0, h1;
            {
                float i_ = ig ? acc[0][rb + 0] : recv[0][rb + 0];
                float f_ = ig ? recv[0][rb + 0] : acc[0][rb + 0];
                float g_ = ig ? acc[1][rb + 0] : recv[1][rb + 0];
                float o_ = ig ? recv[1][rb + 0] : acc[1][rb + 0];
                cst0 = sigf(f_) * cst0 + sigf(i_) * tanhfast(g_);
                h0 = sigf(o_) * tanhfast(cst0);
            }
            {
                float i_ = ig ? acc[0][rb + 1] : recv[0][rb + 1];
                float f_ = ig ? recv[0][rb + 1] : acc[0][rb + 1];
                float g_ = ig ? acc[1][rb + 1] : recv[1][rb + 1];
                float o_ = ig ? recv[1][rb + 1] : acc[1][rb + 1];
                cst1 = sigf(f_) * cst1 + sigf(i_) * tanhfast(g_);
                h1 = sigf(o_) * tanhfast(cst1);
            }

            const uint32_t hw = pack_bf16(h0, h1);
            const int rt = dir ? (Ln - 1 - t) : t;
            __stcg(&g_histB[rt][b_row][hwrd], hw);

            if (t != Ln - 1) {
                // multicast h word to all 8 cluster CTAs (skipped at last step)
                const uint32_t laddr = (t & 1) ? ha1 : ha0;
#pragma unroll
                for (int r = 0; r < 8; r++) {
                    uint32_t raddr;
                    asm("mapa.shared::cluster.u32 %0, %1, %2;" : "=r"(raddr) : "r"(laddr), "r"(r));
                    asm volatile("st.shared::cluster.u32 [%0], %1;" :: "r"(raddr), "r"(hw) : "memory");
                }
                // wait for producers of t+1, then prefetch (overlaps cluster barrier)
                if (tid == 0) wait8(&g_gdone[dir][t + 1]);
                __syncthreads();
                pw[0] = __ldcg(&g_preB[dir][t + 1][bm + grp][wrd0]);
                pw[1] = __ldcg(&g_preB[dir][t + 1][bm + grp + 8][wrd0]);
                pw[2] = __ldcg(&g_preB[dir][t + 1][bm + grp][wrd1]);
                pw[3] = __ldcg(&g_preB[dir][t + 1][bm + grp + 8][wrd1]);
                asm volatile("barrier.cluster.arrive.aligned;" ::: "memory");
                asm volatile("barrier.cluster.wait.aligned;" ::: "memory");
            }
        }

        asm volatile("barrier.cluster.arrive.aligned;" ::: "memory");
        asm volatile("barrier.cluster.wait.aligned;" ::: "memory");
    }
}

// ---------------- 3) emit GEMM (mma bf16): emit[b][t][k] = histB[t][b] @ wemb^T + b_emit ----------------
__global__ void __launch_bounds__(256) k_emit2(const float* __restrict__ bem)
{
    const int t = blockIdx.x;
    __shared__ uint32_t As2[32][136];   // [k2][b]
    __shared__ uint32_t Bs2[32][72];    // [k2][k-col]

    const int tid  = threadIdx.x;
    const int wid  = tid >> 5;
    const int lane = tid & 31;
    const int grp  = lane >> 2;
    const int qk   = lane & 3;
    const int wm   = wid * 16;          // warp batch base

    float acc[8][4];
#pragma unroll
    for (int nb = 0; nb < 8; nb++)
#pragma unroll
        for (int r = 0; r < 4; r++) acc[nb][r] = 0.0f;

    for (int c = 0; c < 8; c++) {                  // K chunks: 64 h (32 words)
        const int k0w = c * 32;
#pragma unroll
        for (int i = 0; i < 4; i++) {              // A: 128 rows x 32 words
            int idx = (i << 8) + tid;
            int r   = idx >> 3;
            int q   = idx & 7;
            uint4 v = *(const uint4*)&g_histB[t][r][k0w + q * 4];
            As2[q * 4 + 0][r] = v.x; As2[q * 4 + 1][r] = v.y;
            As2[q * 4 + 2][r] = v.z; As2[q * 4 + 3][r] = v.w;
        }
#pragma unroll
        for (int i = 0; i < 2; i++) {              // B: 64 rows x 32 words
            int idx = (i << 8) + tid;
            int r   = idx >> 3;
            int q   = idx & 7;
            uint4 v = *(const uint4*)&g_wemb[r][k0w + q * 4];
            Bs2[q * 4 + 0][r] = v.x; Bs2[q * 4 + 1][r] = v.y;
            Bs2[q * 4 + 2][r] = v.z; Bs2[q * 4 + 3][r] = v.w;
        }
        __syncthreads();
#pragma unroll
        for (int kb = 0; kb < 4; kb++) {
            int k2 = kb * 8;
            uint32_t a[4];
            a[0] = As2[k2 + qk][wm + grp];
            a[1] = As2[k2 + qk][wm + grp + 8];
            a[2] = As2[k2 + 4 + qk][wm + grp];
            a[3] = As2[k2 + 4 + qk][wm + grp + 8];
#pragma unroll
            for (int nb = 0; nb < 8; nb++) {
                uint32_t b[2] = {Bs2[k2 + qk][nb * 8 + grp], Bs2[k2 + 4 + qk][nb * 8 + grp]};
                mma_bf16(acc[nb], a, b);
            }
        }
        __syncthreads();
    }

#pragma unroll
    for (int nb = 0; nb < 8; nb++) {
        int k = nb * 8 + qk * 2;
        float b0 = bem[k], b1 = bem[k + 1];
        *(float2*)&g_emit[wm + grp][t][k]     = make_float2(acc[nb][0] + b0, acc[nb][1] + b1);
        *(float2*)&g_emit[wm + grp + 8][t][k] = make_float2(acc[nb][2] + b0, acc[nb][3] + b1);
    }
}

// ---------------- 4) CRF forward + gold score: warp per batch, reduction-free shift ----------------
__global__ void __launch_bounds__(32) k_crf(
    const int* __restrict__ labels,
    const float* __restrict__ trans,
    float* __restrict__ out)
{
    const int b = blockIdx.x;
    const int lane = threadIdx.x;
    __shared__ float ps[64];

    float eTc0[64], eTc1[64];
#pragma unroll 8
    for (int i = 0; i < 64; i++) {
        eTc0[i] = __expf(trans[i * 64 + lane]);
        eTc1[i] = __expf(trans[i * 64 + lane + 32]);
    }

    float d0 = g_emit[b][0][lane];
    float d1 = g_emit[b][0][lane + 32];
    float Cacc = 0.0f, Ckah = 0.0f;

    for (int t = 1; t < Ln; t++) {
        float c = __shfl_sync(0xffffffffu, d0, 0);
        ps[lane]      = __expf(d0 - c);
        ps[lane + 32] = __expf(d1 - c);
        __syncwarp();
        float s0a = 0.f, s0b = 0.f, s1a = 0.f, s1b = 0.f;
#pragma unroll
        for (int i = 0; i < 64; i += 2) {
            float pi = ps[i], pj = ps[i + 1];
            s0a = fmaf(pi, eTc0[i], s0a);
            s0b = fmaf(pj, eTc0[i + 1], s0b);
            s1a = fmaf(pi, eTc1[i], s1a);
            s1b = fmaf(pj, eTc1[i + 1], s1b);
        }
        d0 = g_emit[b][t][lane]      + __logf(s0a + s0b);
        d1 = g_emit[b][t][lane + 32] + __logf(s1a + s1b);
        float y = c - Ckah;
        float tt = Cacc + y;
        Ckah = (tt - Cacc) - y;
        Cacc = tt;
        __syncwarp();
    }

    float m = fmaxf(d0, d1);
#pragma unroll
    for (int o = 16; o > 0; o >>= 1)
        m = fmaxf(m, __shfl_xor_sync(0xffffffffu, m, o));
    float sp = __expf(d0 - m) + __expf(d1 - m);
#pragma unroll
    for (int o = 16; o > 0; o >>= 1)
        sp += __shfl_xor_sync(0xffffffffu, sp, o);
    float logz = m + __logf(sp) + Cacc;

    float gold = 0.0f;
    for (int t = lane; t < Ln; t += 32) {
        int lab = labels[b * Ln + t];
        gold += g_emit[b][t][lab];
        if (t < Ln - 1) {
            int lab2 = labels[b * Ln + t + 1];
            gold += trans[lab * 64 + lab2];
        }
    }
#pragma unroll
    for (int o = 16; o > 0; o >>= 1)
        gold += __shfl_xor_sync(0xffffffffu, gold, o);

    if (lane == 0) out[b] = logz - gold;
}

// ---------------- launch ----------------
extern "C" void kernel_launch(void* const* d_in, const int* in_sizes, int n_in,
                              void* d_out, int out_size)
{
    const float* x     = (const float*)d_in[0];
    const int*   lab   = (const int*)d_in[1];
    const float* wihf  = (const float*)d_in[2];
    const float* whhf  = (const float*)d_in[3];
    const float* bihf  = (const float*)d_in[4];
    const float* bhhf  = (const float*)d_in[5];
    const float* wihb  = (const float*)d_in[6];
    const float* whhb  = (const float*)d_in[7];
    const float* bihb  = (const float*)d_in[8];
    const float* bhhb  = (const float*)d_in[9];
    const float* wem   = (const float*)d_in[10];
    const float* bem   = (const float*)d_in[11];
    const float* trans = (const float*)d_in[12];
    float* out = (float*)d_out;

    k_cvt_x<<<16384, 256>>>(x);                       // also resets g_gdone
    k_cvt_w<<<1088, 256>>>(wihf, wihb, wem);
    k_nop<<<1, 32>>>();                               // keeps ncu capture on the fused kernel
    k_fused<<<8320, 256>>>(whhf, whhb, bihf, bhhf, bihb, bhhb);
    k_emit2<<<512, 256>>>(bem);
    k_crf<<<128, 32>>>(lab, trans, out);
}